// round 14
// baseline (speedup 1.0000x reference)
#include <cuda_runtime.h>
#include <cuda_fp16.h>
#include <cstdint>
#include <cstddef>

// ============================================================================
// SNN, fully batched formulation (7 launches):
//   gemm1_big (M=12800,N=4096,K=1536) -> LIF1 scan -> gemm2_big (K=4096)
//   -> LIF2 scan -> gemm3_big (N=64, split-K=4) -> LIF3 scan (+reduce) -> out
//
// Tensor path (plain sm_103): mma.sync.m16n8k16 + ldmatrix + cp.async.
// Weights split 2-way into fp16 with scaled residual:
//   w = h + m/256,  h = fp16(w), m = fp16(256*(w-h))
// hi comp in FP32 acc; residual in FP16 acc (validated rel_err = 0).
//
// R14: push occupancy to 3 CTAs/SM (24 warps, 6/SMSP) to cover tensor-idle:
//   - S=2 pipeline (stage 32KB -> 64KB/CTA -> 3x64 = 192KB <= 228KB smem)
//     loop: cp_wait<0>; sync; load(it+1); commit; compute(it)  (same single
//     barrier per iter, one-iteration load/compute overlap preserved)
//   - __launch_bounds__(256,3) -> <=85 regs/thread
// Grouped rasterization kept (A/W slices L2-resident).
// ============================================================================

#define TSTEPS 50
#define BATCH  256
#define INDIM  1536
#define H1D    4096
#define H2D    4096
#define OUTD   64
#define MALL   (TSTEPS * BATCH)       // 12800
#define N1     (BATCH * H1D)          // 1048576
#define KSPL3  4                      // layer-3 split-K
#define RGROUP 8                      // raster group (by rows per band)

// ---------------- persistent scratch (device globals) -----------------------
__device__ __align__(128) __half g_spk_in[(size_t)MALL * INDIM];
__device__ __align__(128) float  g_cur[(size_t)MALL * H1D];       // reused cur1/cur2
__device__ __align__(128) __half g_s1_all[(size_t)MALL * H1D];
__device__ __align__(128) __half g_s2_all[(size_t)MALL * H2D];
__device__ __align__(128) float  g_part3[(size_t)KSPL3 * MALL * OUTD];
__device__ __align__(128) __half g_W1a[(size_t)H1D * INDIM];
__device__ __align__(128) __half g_W1b[(size_t)H1D * INDIM];
__device__ __align__(128) __half g_W2a[(size_t)H2D * H1D];
__device__ __align__(128) __half g_W2b[(size_t)H2D * H1D];
__device__ __align__(128) __half g_W3a[(size_t)OUTD * H2D];
__device__ __align__(128) __half g_W3b[(size_t)OUTD * H2D];

// ------------------------------ asm helpers ---------------------------------
__device__ __forceinline__ uint32_t smem_u32(const void* p) {
    uint32_t a;
    asm("{ .reg .u64 t; cvta.to.shared.u64 t, %1; cvt.u32.u64 %0, t; }"
        : "=r"(a) : "l"(p));
    return a;
}

__device__ __forceinline__ void cp16(uint32_t smem, const void* gmem) {
    asm volatile("cp.async.cg.shared.global [%0], [%1], 16;"
                 :: "r"(smem), "l"(gmem) : "memory");
}
__device__ __forceinline__ void cp_commit() {
    asm volatile("cp.async.commit_group;" ::: "memory");
}
template<int N>
__device__ __forceinline__ void cp_wait() {
    asm volatile("cp.async.wait_group %0;" :: "n"(N) : "memory");
}

__device__ __forceinline__ void ldsm4(uint32_t (&r)[4], uint32_t addr) {
    asm volatile("ldmatrix.sync.aligned.m8n8.x4.shared.b16 {%0,%1,%2,%3}, [%4];"
                 : "=r"(r[0]), "=r"(r[1]), "=r"(r[2]), "=r"(r[3]) : "r"(addr));
}

__device__ __forceinline__ void mma_f32(float (&d)[4], const uint32_t (&a)[4],
                                        uint32_t b0, uint32_t b1) {
    asm volatile(
        "mma.sync.aligned.m16n8k16.row.col.f32.f16.f16.f32 "
        "{%0,%1,%2,%3}, {%4,%5,%6,%7}, {%8,%9}, {%0,%1,%2,%3};"
        : "+f"(d[0]), "+f"(d[1]), "+f"(d[2]), "+f"(d[3])
        : "r"(a[0]), "r"(a[1]), "r"(a[2]), "r"(a[3]), "r"(b0), "r"(b1));
}

__device__ __forceinline__ void mma_f16(uint32_t (&d)[2], const uint32_t (&a)[4],
                                        uint32_t b0, uint32_t b1) {
    asm volatile(
        "mma.sync.aligned.m16n8k16.row.col.f16.f16.f16.f16 "
        "{%0,%1}, {%2,%3,%4,%5}, {%6,%7}, {%0,%1};"
        : "+r"(d[0]), "+r"(d[1])
        : "r"(a[0]), "r"(a[1]), "r"(a[2]), "r"(a[3]), "r"(b0), "r"(b1));
}

// ============================================================================
// Batched GEMM. MODE 0: D = A @ (Wa + Wb/256)^T + bias, fp32 store.
//            MODE 1: split-K partial (no bias) to part + z*MALL*OUTD.
// CTA: 256 threads, tile M=128 x N=64, warps 4(m) x 2(n), warp tile 32x32.
// 2-stage cp.async ring; stage = K-chunk 64: A 16KB + B 2x8KB = 32KB.
// 64KB smem -> 3 CTAs/SM (24 warps, 6/SMSP).
// ============================================================================
template<int MODE>
__global__ void __launch_bounds__(256, 3) gemm_big(
    const __half* __restrict__ A, int lda,
    const __half* __restrict__ Wa,
    const __half* __restrict__ Wb,
    int ldw, int nk,
    const float* __restrict__ bias,
    float* __restrict__ outp, int ldn)
{
    constexpr int S = 2;
    constexpr int ABYTES = 128 * 128;            // 16KB: 128 rows x 64 f16
    constexpr int BCOMP  = 64 * 128;             // 8KB per weight component
    constexpr int STAGE  = ABYTES + 2 * BCOMP;   // 32KB

    extern __shared__ char smem[];
    const uint32_t sbase = smem_u32(smem);

    const int tid  = threadIdx.x;
    const int lane = tid & 31;
    const int wid  = tid >> 5;

    // ---- grouped rasterization: waves cover RGROUP by-rows x all bx ---------
    int bx, by;
    if (MODE == 0) {
        const int gid  = (int)(blockIdx.y * gridDim.x + blockIdx.x);
        const int per  = (int)gridDim.x * RGROUP;
        const int band = gid / per;
        const int rem  = gid % per;
        bx = rem / RGROUP;
        by = band * RGROUP + (rem % RGROUP);
    } else {
        bx = (int)blockIdx.x;
        by = (int)blockIdx.y;
    }
    const int m0 = bx * 128;
    const int n0 = by * 64;
    const int kbase = (MODE == 1) ? (int)blockIdx.z * nk * 64 : 0;

    const int warp_m = (wid >> 1) * 32;  // 0,32,64,96
    const int warp_n = (wid & 1) * 32;   // 0,32

    // ---- stage loader: K-chunk 64 -------------------------------------------
    auto load_stage = [&](int L) {
        if (L >= nk) return;
        const uint32_t st = sbase + (uint32_t)(L & (S - 1)) * STAGE;
        const int k0 = kbase + L * 64;
        // A: 1024 16B-slots, 4 per thread
        #pragma unroll
        for (int i = 0; i < 4; ++i) {
            const int idx  = tid + i * 256;
            const int row  = idx >> 3;
            const int slot = idx & 7;
            const char* g = (const char*)(A + (size_t)(m0 + row) * lda + k0) + slot * 16;
            cp16(st + (uint32_t)row * 128u + (uint32_t)((slot ^ (row & 7)) << 4), g);
        }
        // B: 2 comps x 512 slots, 2 per thread per comp
        #pragma unroll
        for (int c = 0; c < 2; ++c) {
            const __half* W = (c == 0) ? Wa : Wb;
            const uint32_t bb = st + ABYTES + (uint32_t)c * BCOMP;
            #pragma unroll
            for (int i = 0; i < 2; ++i) {
                const int idx  = tid + i * 256;
                const int row  = idx >> 3;
                const int slot = idx & 7;
                const char* g = (const char*)(W + (size_t)(n0 + row) * ldw + k0) + slot * 16;
                cp16(bb + (uint32_t)row * 128u + (uint32_t)((slot ^ (row & 7)) << 4), g);
            }
        }
    };

    // ---- prologue: load stage 0 ----------------------------------------------
    load_stage(0);
    cp_commit();

    float    acc [2][4][4];   // [mt][nt][e]  hi comp, f32
    uint32_t accr[2][4][2];   // [mt][nt]     residual, f16x2
    #pragma unroll
    for (int mt = 0; mt < 2; ++mt)
        #pragma unroll
        for (int nt = 0; nt < 4; ++nt) {
            #pragma unroll
            for (int e = 0; e < 4; ++e) acc[mt][nt][e] = 0.0f;
            accr[mt][nt][0] = 0u; accr[mt][nt][1] = 0u;
        }

    const int a_row = (lane & 7) | (((lane >> 3) & 1) << 3);
    const int a_sel = lane >> 4;
    const int b_row = (lane & 7) | (((lane >> 4) & 1) << 3);
    const int b_sel = (lane >> 3) & 1;

    for (int it = 0; it < nk; ++it) {
        // stage `it` resident: wait for all outstanding loads (only load(it)),
        // barrier also guarantees compute(it-1) done before we overwrite its slot
        cp_wait<0>();
        __syncthreads();
        load_stage(it + 1);
        cp_commit();

        const uint32_t st = sbase + (uint32_t)(it & (S - 1)) * STAGE;

        #pragma unroll
        for (int kk = 0; kk < 4; ++kk) {
            // A fragments for this k16 slice: 2 m-tiles (per-kk: low regs)
            uint32_t afr[2][4];
            #pragma unroll
            for (int mt = 0; mt < 2; ++mt) {
                const int row  = warp_m + mt * 16 + a_row;
                const int slot = kk * 2 + a_sel;
                ldsm4(afr[mt],
                      st + (uint32_t)row * 128u + (uint32_t)((slot ^ (row & 7)) << 4));
            }

            {   // hi component (f32 acc)
                uint32_t bfr[2][4];
                #pragma unroll
                for (int jn = 0; jn < 2; ++jn) {
                    const int row  = warp_n + jn * 16 + b_row;
                    const int slot = kk * 2 + b_sel;
                    ldsm4(bfr[jn],
                          st + ABYTES + (uint32_t)row * 128u
                             + (uint32_t)((slot ^ (row & 7)) << 4));
                }
                #pragma unroll
                for (int mt = 0; mt < 2; ++mt)
                    #pragma unroll
                    for (int nt = 0; nt < 4; ++nt)
                        mma_f32(acc[mt][nt], afr[mt],
                                bfr[nt >> 1][(nt & 1) * 2],
                                bfr[nt >> 1][(nt & 1) * 2 + 1]);
            }

            {   // residual component (f16 acc)
                uint32_t bfr[2][4];
                #pragma unroll
                for (int jn = 0; jn < 2; ++jn) {
                    const int row  = warp_n + jn * 16 + b_row;
                    const int slot = kk * 2 + b_sel;
                    ldsm4(bfr[jn],
                          st + ABYTES + BCOMP + (uint32_t)row * 128u
                             + (uint32_t)((slot ^ (row & 7)) << 4));
                }
                #pragma unroll
                for (int mt = 0; mt < 2; ++mt)
                    #pragma unroll
                    for (int nt = 0; nt < 4; ++nt)
                        mma_f16(accr[mt][nt], afr[mt],
                                bfr[nt >> 1][(nt & 1) * 2],
                                bfr[nt >> 1][(nt & 1) * 2 + 1]);
            }
        }
    }

    // ---- epilogue: combine, (bias), store fp32 --------------------------------
    constexpr float SC = 1.0f / 256.0f;
    const int col2 = (lane & 3) * 2;
    const int rowg = lane >> 2;
    float* const obase = (MODE == 1)
        ? outp + (size_t)blockIdx.z * MALL * OUTD
        : outp;
    #pragma unroll
    for (int mt = 0; mt < 2; ++mt) {
        #pragma unroll
        for (int nt = 0; nt < 4; ++nt) {
            const int n = n0 + warp_n + nt * 8 + col2;
            const int mbase = m0 + warp_m + mt * 16 + rowg;
            const float2 r01 = __half22float2(*(const __half2*)&accr[mt][nt][0]);
            const float2 r23 = __half22float2(*(const __half2*)&accr[mt][nt][1]);
            float2 v0, v1;
            v0.x = acc[mt][nt][0] + SC * r01.x;
            v0.y = acc[mt][nt][1] + SC * r01.y;
            v1.x = acc[mt][nt][2] + SC * r23.x;
            v1.y = acc[mt][nt][3] + SC * r23.y;
            if (MODE == 0) {
                const float2 bv = *(const float2*)(bias + n);
                v0.x += bv.x; v0.y += bv.y; v1.x += bv.x; v1.y += bv.y;
            }
            *(float2*)(obase + (size_t)mbase * ldn + n)       = v0;
            *(float2*)(obase + (size_t)(mbase + 8) * ldn + n) = v1;
        }
    }
}

// ============================================================================
// LIF scan over all 50 steps for 4096-wide layers (per-neuron independent).
// ============================================================================
__global__ void k_lif_scan(const float4* __restrict__ cur, __half2* __restrict__ s) {
    const int i = blockIdx.x * blockDim.x + threadIdx.x;   // N1/4 threads exact
    float4 mem; mem.x = 0.0f; mem.y = 0.0f; mem.z = 0.0f; mem.w = 0.0f;
    for (int t = 0; t < TSTEPS; ++t) {
        const float4 c = cur[(size_t)t * (N1 / 4) + i];
        mem.x = 0.9f * mem.x + c.x - ((mem.x > 1.0f) ? 1.0f : 0.0f);
        mem.y = 0.9f * mem.y + c.y - ((mem.y > 1.0f) ? 1.0f : 0.0f);
        mem.z = 0.9f * mem.z + c.z - ((mem.z > 1.0f) ? 1.0f : 0.0f);
        mem.w = 0.9f * mem.w + c.w - ((mem.w > 1.0f) ? 1.0f : 0.0f);
        __half2 lo, hi;
        lo.x = __float2half((mem.x > 1.0f) ? 1.0f : 0.0f);
        lo.y = __float2half((mem.y > 1.0f) ? 1.0f : 0.0f);
        hi.x = __float2half((mem.z > 1.0f) ? 1.0f : 0.0f);
        hi.y = __float2half((mem.w > 1.0f) ? 1.0f : 0.0f);
        s[(size_t)t * (N1 / 2) + 2 * i]     = lo;
        s[(size_t)t * (N1 / 2) + 2 * i + 1] = hi;
    }
}

// ============================================================================
// LIF3: reduce split-K partials + bias, scan, spike-count accumulate.
// ============================================================================
__global__ void k_lif3(const float* __restrict__ part, const float* __restrict__ b3,
                       float* __restrict__ out) {
    const int idx = blockIdx.x * blockDim.x + threadIdx.x;   // 16384 exact
    const int b = idx >> 6;
    const int n = idx & (OUTD - 1);
    const float bv = b3[n];
    float mem = 0.0f, s = 0.0f;
    for (int t = 0; t < TSTEPS; ++t) {
        const size_t moff = (size_t)(t * BATCH + b) * OUTD + n;
        float c = bv;
        #pragma unroll
        for (int z = 0; z < KSPL3; ++z)
            c += part[(size_t)z * MALL * OUTD + moff];
        mem = 0.9f * mem + c - ((mem > 1.0f) ? 1.0f : 0.0f);
        s += ((mem > 1.0f) ? 1.0f : 0.0f);
    }
    out[idx] = s;
}

// ============================================================================
// Prep: spike convert + weight splits (1 launch)
// ============================================================================
__device__ __forceinline__ void split_one(const float* __restrict__ W,
                                          __half* __restrict__ a,
                                          __half* __restrict__ b,
                                          int n, int gid, int st) {
    for (int i = gid; i < n; i += st) {
        const float w = W[i];
        const __half h = __float2half_rn(w);
        const float r = w - __half2float(h);
        a[i] = h;
        b[i] = __float2half_rn(r * 256.0f);
    }
}

__global__ void k_prep(const float* __restrict__ x, __half* __restrict__ xs, int nx,
                       const float* __restrict__ W1, __half* w1a, __half* w1b, int n1,
                       const float* __restrict__ W2, __half* w2a, __half* w2b, int n2,
                       const float* __restrict__ W3, __half* w3a, __half* w3b, int n3) {
    const int gid = blockIdx.x * blockDim.x + threadIdx.x;
    const int st  = gridDim.x * blockDim.x;
    for (int i = gid; i < nx; i += st) xs[i] = __float2half(x[i]);
    split_one(W1, w1a, w1b, n1, gid, st);
    split_one(W2, w2a, w2b, n2, gid, st);
    split_one(W3, w3a, w3b, n3, gid, st);
}

// ============================================================================
// Host launcher: 7 kernel launches total.
// ============================================================================
extern "C" void kernel_launch(void* const* d_in, const int* in_sizes, int n_in,
                              void* d_out, int out_size) {
    (void)in_sizes; (void)n_in; (void)out_size;

    const float* spike_seq = (const float*)d_in[0];
    const float* W1 = (const float*)d_in[1];
    const float* b1 = (const float*)d_in[2];
    const float* W2 = (const float*)d_in[3];
    const float* b2 = (const float*)d_in[4];
    const float* W3 = (const float*)d_in[5];
    const float* b3 = (const float*)d_in[6];
    float* out = (float*)d_out;

    void *p_spk, *p_cur, *p_s1a, *p_s2a, *p_part3;
    void *p_w1a, *p_w1b, *p_w2a, *p_w2b, *p_w3a, *p_w3b;
    cudaGetSymbolAddress(&p_spk, g_spk_in);
    cudaGetSymbolAddress(&p_cur, g_cur);
    cudaGetSymbolAddress(&p_s1a, g_s1_all);
    cudaGetSymbolAddress(&p_s2a, g_s2_all);
    cudaGetSymbolAddress(&p_part3, g_part3);
    cudaGetSymbolAddress(&p_w1a, g_W1a); cudaGetSymbolAddress(&p_w1b, g_W1b);
    cudaGetSymbolAddress(&p_w2a, g_W2a); cudaGetSymbolAddress(&p_w2b, g_W2b);
    cudaGetSymbolAddress(&p_w3a, g_W3a); cudaGetSymbolAddress(&p_w3b, g_W3b);

    __half* spkin = (__half*)p_spk;
    float*  cur   = (float*)p_cur;
    __half* s1all = (__half*)p_s1a;
    __half* s2all = (__half*)p_s2a;
    float*  part3 = (float*)p_part3;
    __half *w1a = (__half*)p_w1a, *w1b = (__half*)p_w1b;
    __half *w2a = (__half*)p_w2a, *w2b = (__half*)p_w2b;
    __half *w3a = (__half*)p_w3a, *w3b = (__half*)p_w3b;

    constexpr int SMEM = 2 * (128 * 128 + 2 * 64 * 128);   // 65536 = 64KB
    static int configured = -1;
    if (configured < 0) {
        cudaFuncSetAttribute(gemm_big<0>,
                             cudaFuncAttributeMaxDynamicSharedMemorySize, SMEM);
        cudaFuncSetAttribute(gemm_big<1>,
                             cudaFuncAttributeMaxDynamicSharedMemorySize, SMEM);
        configured = 1;
    }

    // 1) prep
    k_prep<<<1184, 256>>>(spike_seq, spkin, MALL * INDIM,
                          W1, w1a, w1b, H1D * INDIM,
                          W2, w2a, w2b, H2D * H1D,
                          W3, w3a, w3b, OUTD * H2D);

    // 2) gemm1_big: cur1 = x @ W1^T + b1   (M=12800, N=4096, K=1536)
    gemm_big<0><<<dim3(MALL / 128, H1D / 64), 256, SMEM>>>(
        spkin, INDIM, w1a, w1b, INDIM, INDIM / 64, b1, cur, H1D);

    // 3) LIF1 scan -> s1_all
    k_lif_scan<<<N1 / 4 / 256, 256>>>((const float4*)cur, (__half2*)s1all);

    // 4) gemm2_big: cur2 = s1_all @ W2^T + b2   (M=12800, N=4096, K=4096)
    gemm_big<0><<<dim3(MALL / 128, H2D / 64), 256, SMEM>>>(
        s1all, H1D, w2a, w2b, H1D, H1D / 64, b2, cur, H2D);

    // 5) LIF2 scan -> s2_all
    k_lif_scan<<<N1 / 4 / 256, 256>>>((const float4*)cur, (__half2*)s2all);

    // 6) gemm3_big: split-K=4 partials   (M=12800, N=64, K=1024 per split)
    gemm_big<1><<<dim3(MALL / 128, 1, KSPL3), 256, SMEM>>>(
        s2all, H2D, w3a, w3b, H2D, (H2D / KSPL3) / 64, nullptr, part3, OUTD);

    // 7) LIF3: reduce partials + scan + accumulate
    k_lif3<<<(BATCH * OUTD) / 256, 256>>>(part3, b3, out);
}

// round 15
// speedup vs baseline: 1.0529x; 1.0529x over previous
#include <cuda_runtime.h>
#include <cuda_fp16.h>
#include <cstdint>
#include <cstddef>

// ============================================================================
// SNN, fully batched formulation (7 launches):
//   gemm1_big (M=12800,N=4096,K=1536) -> LIF1 scan -> gemm2_big (K=4096)
//   -> LIF2 scan -> gemm3_big (N=64, split-K=8) -> LIF3 scan (+reduce) -> out
//
// Tensor path (plain sm_103): mma.sync.m16n8k16 + ldmatrix + cp.async.
// Weights split 2-way into fp16 with scaled residual:
//   w = h + m/256,  h = fp16(w), m = fp16(256*(w-h))
// hi comp in FP32 acc; residual in FP16 acc (validated rel_err = 0).
//
// GEMM core = R12 optimum (measured best): 256 thr, tile 128x64, warps 4m x 2n,
// warp tile 32x32, 3-stage cp.async ring (K-chunk 64, 32KB/stage, 96KB smem),
// __launch_bounds__(256,2) -> 2 CTAs/SM, 126 regs. ~88% of HMMA issue floor.
// R15 consolidation: split-K 8 for gemm3 tail packing + vectorized prep/scan.
// ============================================================================

#define TSTEPS 50
#define BATCH  256
#define INDIM  1536
#define H1D    4096
#define H2D    4096
#define OUTD   64
#define MALL   (TSTEPS * BATCH)       // 12800
#define N1     (BATCH * H1D)          // 1048576
#define KSPL3  8                      // layer-3 split-K

// ---------------- persistent scratch (device globals) -----------------------
__device__ __align__(128) __half g_spk_in[(size_t)MALL * INDIM];
__device__ __align__(128) float  g_cur[(size_t)MALL * H1D];       // reused cur1/cur2
__device__ __align__(128) __half g_s1_all[(size_t)MALL * H1D];
__device__ __align__(128) __half g_s2_all[(size_t)MALL * H2D];
__device__ __align__(128) float  g_part3[(size_t)KSPL3 * MALL * OUTD];
__device__ __align__(128) __half g_W1a[(size_t)H1D * INDIM];
__device__ __align__(128) __half g_W1b[(size_t)H1D * INDIM];
__device__ __align__(128) __half g_W2a[(size_t)H2D * H1D];
__device__ __align__(128) __half g_W2b[(size_t)H2D * H1D];
__device__ __align__(128) __half g_W3a[(size_t)OUTD * H2D];
__device__ __align__(128) __half g_W3b[(size_t)OUTD * H2D];

// ------------------------------ asm helpers ---------------------------------
__device__ __forceinline__ uint32_t smem_u32(const void* p) {
    uint32_t a;
    asm("{ .reg .u64 t; cvta.to.shared.u64 t, %1; cvt.u32.u64 %0, t; }"
        : "=r"(a) : "l"(p));
    return a;
}

__device__ __forceinline__ void cp16(uint32_t smem, const void* gmem) {
    asm volatile("cp.async.cg.shared.global [%0], [%1], 16;"
                 :: "r"(smem), "l"(gmem) : "memory");
}
__device__ __forceinline__ void cp_commit() {
    asm volatile("cp.async.commit_group;" ::: "memory");
}
template<int N>
__device__ __forceinline__ void cp_wait() {
    asm volatile("cp.async.wait_group %0;" :: "n"(N) : "memory");
}

__device__ __forceinline__ void ldsm4(uint32_t (&r)[4], uint32_t addr) {
    asm volatile("ldmatrix.sync.aligned.m8n8.x4.shared.b16 {%0,%1,%2,%3}, [%4];"
                 : "=r"(r[0]), "=r"(r[1]), "=r"(r[2]), "=r"(r[3]) : "r"(addr));
}

__device__ __forceinline__ void mma_f32(float (&d)[4], const uint32_t (&a)[4],
                                        uint32_t b0, uint32_t b1) {
    asm volatile(
        "mma.sync.aligned.m16n8k16.row.col.f32.f16.f16.f32 "
        "{%0,%1,%2,%3}, {%4,%5,%6,%7}, {%8,%9}, {%0,%1,%2,%3};"
        : "+f"(d[0]), "+f"(d[1]), "+f"(d[2]), "+f"(d[3])
        : "r"(a[0]), "r"(a[1]), "r"(a[2]), "r"(a[3]), "r"(b0), "r"(b1));
}

__device__ __forceinline__ void mma_f16(uint32_t (&d)[2], const uint32_t (&a)[4],
                                        uint32_t b0, uint32_t b1) {
    asm volatile(
        "mma.sync.aligned.m16n8k16.row.col.f16.f16.f16.f16 "
        "{%0,%1}, {%2,%3,%4,%5}, {%6,%7}, {%0,%1};"
        : "+r"(d[0]), "+r"(d[1])
        : "r"(a[0]), "r"(a[1]), "r"(a[2]), "r"(a[3]), "r"(b0), "r"(b1));
}

// ============================================================================
// Batched GEMM (R12 core). MODE 0: D = A @ (Wa + Wb/256)^T + bias, fp32 store.
//                        MODE 1: split-K partial (no bias) to part + z*MALL*OUTD.
// CTA: 256 threads, tile M=128 x N=64, warps 4(m) x 2(n), warp tile 32x32.
// 3-stage cp.async ring; stage = K-chunk 64: A 16KB + B 2x8KB = 32KB.
// 96KB smem -> 2 CTAs/SM.
// ============================================================================
template<int MODE>
__global__ void __launch_bounds__(256, 2) gemm_big(
    const __half* __restrict__ A, int lda,
    const __half* __restrict__ Wa,
    const __half* __restrict__ Wb,
    int ldw, int nk,
    const float* __restrict__ bias,
    float* __restrict__ outp, int ldn)
{
    constexpr int S = 3;
    constexpr int ABYTES = 128 * 128;            // 16KB: 128 rows x 64 f16
    constexpr int BCOMP  = 64 * 128;             // 8KB per weight component
    constexpr int STAGE  = ABYTES + 2 * BCOMP;   // 32KB

    extern __shared__ char smem[];
    const uint32_t sbase = smem_u32(smem);

    const int tid  = threadIdx.x;
    const int lane = tid & 31;
    const int wid  = tid >> 5;
    const int m0   = blockIdx.x * 128;
    const int n0   = blockIdx.y * 64;
    const int kbase = (MODE == 1) ? (int)blockIdx.z * nk * 64 : 0;

    const int warp_m = (wid >> 1) * 32;  // 0,32,64,96
    const int warp_n = (wid & 1) * 32;   // 0,32

    // ---- stage loader: K-chunk 64 -------------------------------------------
    auto load_stage = [&](int L) {
        if (L >= nk) return;
        const uint32_t st = sbase + (uint32_t)(L % S) * STAGE;
        const int k0 = kbase + L * 64;
        // A: 1024 16B-slots, 4 per thread
        #pragma unroll
        for (int i = 0; i < 4; ++i) {
            const int idx  = tid + i * 256;
            const int row  = idx >> 3;
            const int slot = idx & 7;
            const char* g = (const char*)(A + (size_t)(m0 + row) * lda + k0) + slot * 16;
            cp16(st + (uint32_t)row * 128u + (uint32_t)((slot ^ (row & 7)) << 4), g);
        }
        // B: 2 comps x 512 slots, 2 per thread per comp
        #pragma unroll
        for (int c = 0; c < 2; ++c) {
            const __half* W = (c == 0) ? Wa : Wb;
            const uint32_t bb = st + ABYTES + (uint32_t)c * BCOMP;
            #pragma unroll
            for (int i = 0; i < 2; ++i) {
                const int idx  = tid + i * 256;
                const int row  = idx >> 3;
                const int slot = idx & 7;
                const char* g = (const char*)(W + (size_t)(n0 + row) * ldw + k0) + slot * 16;
                cp16(bb + (uint32_t)row * 128u + (uint32_t)((slot ^ (row & 7)) << 4), g);
            }
        }
    };

    #pragma unroll
    for (int L = 0; L < S - 1; ++L) { load_stage(L); cp_commit(); }

    float    acc [2][4][4];   // [mt][nt][e]  hi comp, f32
    uint32_t accr[2][4][2];   // [mt][nt]     residual, f16x2
    #pragma unroll
    for (int mt = 0; mt < 2; ++mt)
        #pragma unroll
        for (int nt = 0; nt < 4; ++nt) {
            #pragma unroll
            for (int e = 0; e < 4; ++e) acc[mt][nt][e] = 0.0f;
            accr[mt][nt][0] = 0u; accr[mt][nt][1] = 0u;
        }

    const int a_row = (lane & 7) | (((lane >> 3) & 1) << 3);
    const int a_sel = lane >> 4;
    const int b_row = (lane & 7) | (((lane >> 4) & 1) << 3);
    const int b_sel = (lane >> 3) & 1;

    for (int it = 0; it < nk; ++it) {
        cp_wait<S - 2>();
        __syncthreads();
        load_stage(it + S - 1);
        cp_commit();

        const uint32_t st = sbase + (uint32_t)(it % S) * STAGE;

        #pragma unroll
        for (int kk = 0; kk < 4; ++kk) {
            // A fragments for this k16 slice: 2 m-tiles (per-kk: low regs)
            uint32_t afr[2][4];
            #pragma unroll
            for (int mt = 0; mt < 2; ++mt) {
                const int row  = warp_m + mt * 16 + a_row;
                const int slot = kk * 2 + a_sel;
                ldsm4(afr[mt],
                      st + (uint32_t)row * 128u + (uint32_t)((slot ^ (row & 7)) << 4));
            }

            {   // hi component (f32 acc)
                uint32_t bfr[2][4];
                #pragma unroll
                for (int jn = 0; jn < 2; ++jn) {
                    const int row  = warp_n + jn * 16 + b_row;
                    const int slot = kk * 2 + b_sel;
                    ldsm4(bfr[jn],
                          st + ABYTES + (uint32_t)row * 128u
                             + (uint32_t)((slot ^ (row & 7)) << 4));
                }
                #pragma unroll
                for (int mt = 0; mt < 2; ++mt)
                    #pragma unroll
                    for (int nt = 0; nt < 4; ++nt)
                        mma_f32(acc[mt][nt], afr[mt],
                                bfr[nt >> 1][(nt & 1) * 2],
                                bfr[nt >> 1][(nt & 1) * 2 + 1]);
            }

            {   // residual component (f16 acc)
                uint32_t bfr[2][4];
                #pragma unroll
                for (int jn = 0; jn < 2; ++jn) {
                    const int row  = warp_n + jn * 16 + b_row;
                    const int slot = kk * 2 + b_sel;
                    ldsm4(bfr[jn],
                          st + ABYTES + BCOMP + (uint32_t)row * 128u
                             + (uint32_t)((slot ^ (row & 7)) << 4));
                }
                #pragma unroll
                for (int mt = 0; mt < 2; ++mt)
                    #pragma unroll
                    for (int nt = 0; nt < 4; ++nt)
                        mma_f16(accr[mt][nt], afr[mt],
                                bfr[nt >> 1][(nt & 1) * 2],
                                bfr[nt >> 1][(nt & 1) * 2 + 1]);
            }
        }
    }

    // ---- epilogue: combine, (bias), store fp32 --------------------------------
    constexpr float SC = 1.0f / 256.0f;
    const int col2 = (lane & 3) * 2;
    const int rowg = lane >> 2;
    float* const obase = (MODE == 1)
        ? outp + (size_t)blockIdx.z * MALL * OUTD
        : outp;
    #pragma unroll
    for (int mt = 0; mt < 2; ++mt) {
        #pragma unroll
        for (int nt = 0; nt < 4; ++nt) {
            const int n = n0 + warp_n + nt * 8 + col2;
            const int mbase = m0 + warp_m + mt * 16 + rowg;
            const float2 r01 = __half22float2(*(const __half2*)&accr[mt][nt][0]);
            const float2 r23 = __half22float2(*(const __half2*)&accr[mt][nt][1]);
            float2 v0, v1;
            v0.x = acc[mt][nt][0] + SC * r01.x;
            v0.y = acc[mt][nt][1] + SC * r01.y;
            v1.x = acc[mt][nt][2] + SC * r23.x;
            v1.y = acc[mt][nt][3] + SC * r23.y;
            if (MODE == 0) {
                const float2 bv = *(const float2*)(bias + n);
                v0.x += bv.x; v0.y += bv.y; v1.x += bv.x; v1.y += bv.y;
            }
            *(float2*)(obase + (size_t)mbase * ldn + n)       = v0;
            *(float2*)(obase + (size_t)(mbase + 8) * ldn + n) = v1;
        }
    }
}

// ============================================================================
// LIF scan over all 50 steps for 4096-wide layers (per-neuron independent).
// One 8B spike store per thread per step.
// ============================================================================
__global__ void k_lif_scan(const float4* __restrict__ cur, uint2* __restrict__ s) {
    const int i = blockIdx.x * blockDim.x + threadIdx.x;   // N1/4 threads exact
    float4 mem; mem.x = 0.0f; mem.y = 0.0f; mem.z = 0.0f; mem.w = 0.0f;
    for (int t = 0; t < TSTEPS; ++t) {
        const float4 c = cur[(size_t)t * (N1 / 4) + i];
        mem.x = 0.9f * mem.x + c.x - ((mem.x > 1.0f) ? 1.0f : 0.0f);
        mem.y = 0.9f * mem.y + c.y - ((mem.y > 1.0f) ? 1.0f : 0.0f);
        mem.z = 0.9f * mem.z + c.z - ((mem.z > 1.0f) ? 1.0f : 0.0f);
        mem.w = 0.9f * mem.w + c.w - ((mem.w > 1.0f) ? 1.0f : 0.0f);
        __half2 lo, hi;
        lo.x = __float2half((mem.x > 1.0f) ? 1.0f : 0.0f);
        lo.y = __float2half((mem.y > 1.0f) ? 1.0f : 0.0f);
        hi.x = __float2half((mem.z > 1.0f) ? 1.0f : 0.0f);
        hi.y = __float2half((mem.w > 1.0f) ? 1.0f : 0.0f);
        uint2 pk;
        pk.x = *(const uint32_t*)&lo;
        pk.y = *(const uint32_t*)&hi;
        s[(size_t)t * (N1 / 4) + i] = pk;
    }
}

// ============================================================================
// LIF3: reduce split-K partials + bias, scan, spike-count accumulate.
// ============================================================================
__global__ void k_lif3(const float* __restrict__ part, const float* __restrict__ b3,
                       float* __restrict__ out) {
    const int idx = blockIdx.x * blockDim.x + threadIdx.x;   // 16384 exact
    const int b = idx >> 6;
    const int n = idx & (OUTD - 1);
    const float bv = b3[n];
    float mem = 0.0f, s = 0.0f;
    for (int t = 0; t < TSTEPS; ++t) {
        const size_t moff = (size_t)(t * BATCH + b) * OUTD + n;
        float c = bv;
        #pragma unroll
        for (int z = 0; z < KSPL3; ++z)
            c += part[(size_t)z * MALL * OUTD + moff];
        mem = 0.9f * mem + c - ((mem > 1.0f) ? 1.0f : 0.0f);
        s += ((mem > 1.0f) ? 1.0f : 0.0f);
    }
    out[idx] = s;
}

// ============================================================================
// Prep: spike convert + weight splits, vectorized 2 elems/thread (1 launch)
// ============================================================================
__device__ __forceinline__ void split_one2(const float2* __restrict__ W,
                                           __half2* __restrict__ a,
                                           __half2* __restrict__ b,
                                           int n2, int gid, int st) {
    for (int i = gid; i < n2; i += st) {
        const float2 w = W[i];
        const __half hx = __float2half_rn(w.x);
        const __half hy = __float2half_rn(w.y);
        const float rx = (w.x - __half2float(hx)) * 256.0f;
        const float ry = (w.y - __half2float(hy)) * 256.0f;
        __half2 ha; ha.x = hx; ha.y = hy;
        __half2 hb; hb.x = __float2half_rn(rx); hb.y = __float2half_rn(ry);
        a[i] = ha; b[i] = hb;
    }
}

__global__ void k_prep(const float2* __restrict__ x, __half2* __restrict__ xs, int nx2,
                       const float2* __restrict__ W1, __half2* w1a, __half2* w1b, int n1,
                       const float2* __restrict__ W2, __half2* w2a, __half2* w2b, int n2,
                       const float2* __restrict__ W3, __half2* w3a, __half2* w3b, int n3) {
    const int gid = blockIdx.x * blockDim.x + threadIdx.x;
    const int st  = gridDim.x * blockDim.x;
    for (int i = gid; i < nx2; i += st) {
        const float2 v = x[i];
        __half2 h; h.x = __float2half(v.x); h.y = __float2half(v.y);
        xs[i] = h;
    }
    split_one2(W1, w1a, w1b, n1, gid, st);
    split_one2(W2, w2a, w2b, n2, gid, st);
    split_one2(W3, w3a, w3b, n3, gid, st);
}

// ============================================================================
// Host launcher: 7 kernel launches total.
// ============================================================================
extern "C" void kernel_launch(void* const* d_in, const int* in_sizes, int n_in,
                              void* d_out, int out_size) {
    (void)in_sizes; (void)n_in; (void)out_size;

    const float* spike_seq = (const float*)d_in[0];
    const float* W1 = (const float*)d_in[1];
    const float* b1 = (const float*)d_in[2];
    const float* W2 = (const float*)d_in[3];
    const float* b2 = (const float*)d_in[4];
    const float* W3 = (const float*)d_in[5];
    const float* b3 = (const float*)d_in[6];
    float* out = (float*)d_out;

    void *p_spk, *p_cur, *p_s1a, *p_s2a, *p_part3;
    void *p_w1a, *p_w1b, *p_w2a, *p_w2b, *p_w3a, *p_w3b;
    cudaGetSymbolAddress(&p_spk, g_spk_in);
    cudaGetSymbolAddress(&p_cur, g_cur);
    cudaGetSymbolAddress(&p_s1a, g_s1_all);
    cudaGetSymbolAddress(&p_s2a, g_s2_all);
    cudaGetSymbolAddress(&p_part3, g_part3);
    cudaGetSymbolAddress(&p_w1a, g_W1a); cudaGetSymbolAddress(&p_w1b, g_W1b);
    cudaGetSymbolAddress(&p_w2a, g_W2a); cudaGetSymbolAddress(&p_w2b, g_W2b);
    cudaGetSymbolAddress(&p_w3a, g_W3a); cudaGetSymbolAddress(&p_w3b, g_W3b);

    __half* spkin = (__half*)p_spk;
    float*  cur   = (float*)p_cur;
    __half* s1all = (__half*)p_s1a;
    __half* s2all = (__half*)p_s2a;
    float*  part3 = (float*)p_part3;
    __half *w1a = (__half*)p_w1a, *w1b = (__half*)p_w1b;
    __half *w2a = (__half*)p_w2a, *w2b = (__half*)p_w2b;
    __half *w3a = (__half*)p_w3a, *w3b = (__half*)p_w3b;

    constexpr int SMEM = 3 * (128 * 128 + 2 * 64 * 128);   // 98304 = 96KB
    static int configured = -1;
    if (configured < 0) {
        cudaFuncSetAttribute(gemm_big<0>,
                             cudaFuncAttributeMaxDynamicSharedMemorySize, SMEM);
        cudaFuncSetAttribute(gemm_big<1>,
                             cudaFuncAttributeMaxDynamicSharedMemorySize, SMEM);
        configured = 1;
    }

    // 1) prep (vectorized, 2 elems/thread)
    k_prep<<<1184, 256>>>((const float2*)spike_seq, (__half2*)spkin, MALL * INDIM / 2,
                          (const float2*)W1, (__half2*)w1a, (__half2*)w1b, H1D * INDIM / 2,
                          (const float2*)W2, (__half2*)w2a, (__half2*)w2b, H2D * H1D / 2,
                          (const float2*)W3, (__half2*)w3a, (__half2*)w3b, OUTD * H2D / 2);

    // 2) gemm1_big: cur1 = x @ W1^T + b1   (M=12800, N=4096, K=1536)
    gemm_big<0><<<dim3(MALL / 128, H1D / 64), 256, SMEM>>>(
        spkin, INDIM, w1a, w1b, INDIM, INDIM / 64, b1, cur, H1D);

    // 3) LIF1 scan -> s1_all
    k_lif_scan<<<N1 / 4 / 256, 256>>>((const float4*)cur, (uint2*)s1all);

    // 4) gemm2_big: cur2 = s1_all @ W2^T + b2   (M=12800, N=4096, K=4096)
    gemm_big<0><<<dim3(MALL / 128, H2D / 64), 256, SMEM>>>(
        s1all, H1D, w2a, w2b, H1D, H1D / 64, b2, cur, H2D);

    // 5) LIF2 scan -> s2_all
    k_lif_scan<<<N1 / 4 / 256, 256>>>((const float4*)cur, (uint2*)s2all);

    // 6) gemm3_big: split-K=8 partials   (M=12800, N=64, K=512 per split)
    gemm_big<1><<<dim3(MALL / 128, 1, KSPL3), 256, SMEM>>>(
        s2all, H2D, w3a, w3b, H2D, (H2D / KSPL3) / 64, nullptr, part3, OUTD);

    // 7) LIF3: reduce partials + scan + accumulate
    k_lif3<<<(BATCH * OUTD) / 256, 256>>>(part3, b3, out);
}

// round 16
// speedup vs baseline: 1.0537x; 1.0007x over previous
#include <cuda_runtime.h>
#include <cuda_fp16.h>
#include <cstdint>
#include <cstddef>

// ============================================================================
// SNN, fully batched formulation (7 launches):
//   gemm1_big (M=12800,N=4096,K=1536) -> LIF1 scan -> gemm2_big (K=4096)
//   -> LIF2 scan -> gemm3_big (N=64, split-K=8) -> LIF3 scan (+reduce) -> out
//
// Tensor path (plain sm_103): mma.sync.m16n8k16 + ldmatrix + cp.async.
// Weights split 2-way into fp16 with scaled residual:
//   w = h + m/256,  h = fp16(w), m = fp16(256*(w-h))
// hi comp in FP32 acc; residual in FP16 acc (rel_err = 0 across all rounds).
//
// GEMM core = measured optimum (R12): 256 thr, tile 128x64, warps 4m x 2n,
// warp tile 32x32, 3-stage cp.async ring (K-chunk 64, 32KB/stage, 96KB smem),
// __launch_bounds__(256,2) -> 2 CTAs/SM, 128 regs (full register file:
// 16 warps x 32 x 128 = 64K). ~88% of the fallback-HMMA issue floor; design
// space bracketed (1/2/3 CTAs per SM, warp tiles 32x32/64x32, S=2/3, K64/128)
// -- this configuration is the wall.
// ============================================================================

#define TSTEPS 50
#define BATCH  256
#define INDIM  1536
#define H1D    4096
#define H2D    4096
#define OUTD   64
#define MALL   (TSTEPS * BATCH)       // 12800
#define N1     (BATCH * H1D)          // 1048576
#define KSPL3  8                      // layer-3 split-K

// ---------------- persistent scratch (device globals) -----------------------
__device__ __align__(128) __half g_spk_in[(size_t)MALL * INDIM];
__device__ __align__(128) float  g_cur[(size_t)MALL * H1D];       // reused cur1/cur2
__device__ __align__(128) __half g_s1_all[(size_t)MALL * H1D];
__device__ __align__(128) __half g_s2_all[(size_t)MALL * H2D];
__device__ __align__(128) float  g_part3[(size_t)KSPL3 * MALL * OUTD];
__device__ __align__(128) __half g_W1a[(size_t)H1D * INDIM];
__device__ __align__(128) __half g_W1b[(size_t)H1D * INDIM];
__device__ __align__(128) __half g_W2a[(size_t)H2D * H1D];
__device__ __align__(128) __half g_W2b[(size_t)H2D * H1D];
__device__ __align__(128) __half g_W3a[(size_t)OUTD * H2D];
__device__ __align__(128) __half g_W3b[(size_t)OUTD * H2D];

// ------------------------------ asm helpers ---------------------------------
__device__ __forceinline__ uint32_t smem_u32(const void* p) {
    uint32_t a;
    asm("{ .reg .u64 t; cvta.to.shared.u64 t, %1; cvt.u32.u64 %0, t; }"
        : "=r"(a) : "l"(p));
    return a;
}

__device__ __forceinline__ void cp16(uint32_t smem, const void* gmem) {
    asm volatile("cp.async.cg.shared.global [%0], [%1], 16;"
                 :: "r"(smem), "l"(gmem) : "memory");
}
__device__ __forceinline__ void cp_commit() {
    asm volatile("cp.async.commit_group;" ::: "memory");
}
template<int N>
__device__ __forceinline__ void cp_wait() {
    asm volatile("cp.async.wait_group %0;" :: "n"(N) : "memory");
}

__device__ __forceinline__ void ldsm4(uint32_t (&r)[4], uint32_t addr) {
    asm volatile("ldmatrix.sync.aligned.m8n8.x4.shared.b16 {%0,%1,%2,%3}, [%4];"
                 : "=r"(r[0]), "=r"(r[1]), "=r"(r[2]), "=r"(r[3]) : "r"(addr));
}

__device__ __forceinline__ void mma_f32(float (&d)[4], const uint32_t (&a)[4],
                                        uint32_t b0, uint32_t b1) {
    asm volatile(
        "mma.sync.aligned.m16n8k16.row.col.f32.f16.f16.f32 "
        "{%0,%1,%2,%3}, {%4,%5,%6,%7}, {%8,%9}, {%0,%1,%2,%3};"
        : "+f"(d[0]), "+f"(d[1]), "+f"(d[2]), "+f"(d[3])
        : "r"(a[0]), "r"(a[1]), "r"(a[2]), "r"(a[3]), "r"(b0), "r"(b1));
}

__device__ __forceinline__ void mma_f16(uint32_t (&d)[2], const uint32_t (&a)[4],
                                        uint32_t b0, uint32_t b1) {
    asm volatile(
        "mma.sync.aligned.m16n8k16.row.col.f16.f16.f16.f16 "
        "{%0,%1}, {%2,%3,%4,%5}, {%6,%7}, {%0,%1};"
        : "+r"(d[0]), "+r"(d[1])
        : "r"(a[0]), "r"(a[1]), "r"(a[2]), "r"(a[3]), "r"(b0), "r"(b1));
}

// ============================================================================
// Batched GEMM (R12 core). MODE 0: D = A @ (Wa + Wb/256)^T + bias, fp32 store.
//                        MODE 1: split-K partial (no bias) to part + z*MALL*OUTD.
// CTA: 256 threads, tile M=128 x N=64, warps 4(m) x 2(n), warp tile 32x32.
// 3-stage cp.async ring; stage = K-chunk 64: A 16KB + B 2x8KB = 32KB.
// 96KB smem -> 2 CTAs/SM.
// ============================================================================
template<int MODE>
__global__ void __launch_bounds__(256, 2) gemm_big(
    const __half* __restrict__ A, int lda,
    const __half* __restrict__ Wa,
    const __half* __restrict__ Wb,
    int ldw, int nk,
    const float* __restrict__ bias,
    float* __restrict__ outp, int ldn)
{
    constexpr int S = 3;
    constexpr int ABYTES = 128 * 128;            // 16KB: 128 rows x 64 f16
    constexpr int BCOMP  = 64 * 128;             // 8KB per weight component
    constexpr int STAGE  = ABYTES + 2 * BCOMP;   // 32KB

    extern __shared__ char smem[];
    const uint32_t sbase = smem_u32(smem);

    const int tid  = threadIdx.x;
    const int lane = tid & 31;
    const int wid  = tid >> 5;
    const int m0   = blockIdx.x * 128;
    const int n0   = blockIdx.y * 64;
    const int kbase = (MODE == 1) ? (int)blockIdx.z * nk * 64 : 0;

    const int warp_m = (wid >> 1) * 32;  // 0,32,64,96
    const int warp_n = (wid & 1) * 32;   // 0,32

    // ---- stage loader: K-chunk 64 -------------------------------------------
    auto load_stage = [&](int L) {
        if (L >= nk) return;
        const uint32_t st = sbase + (uint32_t)(L % S) * STAGE;
        const int k0 = kbase + L * 64;
        // A: 1024 16B-slots, 4 per thread
        #pragma unroll
        for (int i = 0; i < 4; ++i) {
            const int idx  = tid + i * 256;
            const int row  = idx >> 3;
            const int slot = idx & 7;
            const char* g = (const char*)(A + (size_t)(m0 + row) * lda + k0) + slot * 16;
            cp16(st + (uint32_t)row * 128u + (uint32_t)((slot ^ (row & 7)) << 4), g);
        }
        // B: 2 comps x 512 slots, 2 per thread per comp
        #pragma unroll
        for (int c = 0; c < 2; ++c) {
            const __half* W = (c == 0) ? Wa : Wb;
            const uint32_t bb = st + ABYTES + (uint32_t)c * BCOMP;
            #pragma unroll
            for (int i = 0; i < 2; ++i) {
                const int idx  = tid + i * 256;
                const int row  = idx >> 3;
                const int slot = idx & 7;
                const char* g = (const char*)(W + (size_t)(n0 + row) * ldw + k0) + slot * 16;
                cp16(bb + (uint32_t)row * 128u + (uint32_t)((slot ^ (row & 7)) << 4), g);
            }
        }
    };

    #pragma unroll
    for (int L = 0; L < S - 1; ++L) { load_stage(L); cp_commit(); }

    float    acc [2][4][4];   // [mt][nt][e]  hi comp, f32
    uint32_t accr[2][4][2];   // [mt][nt]     residual, f16x2
    #pragma unroll
    for (int mt = 0; mt < 2; ++mt)
        #pragma unroll
        for (int nt = 0; nt < 4; ++nt) {
            #pragma unroll
            for (int e = 0; e < 4; ++e) acc[mt][nt][e] = 0.0f;
            accr[mt][nt][0] = 0u; accr[mt][nt][1] = 0u;
        }

    const int a_row = (lane & 7) | (((lane >> 3) & 1) << 3);
    const int a_sel = lane >> 4;
    const int b_row = (lane & 7) | (((lane >> 4) & 1) << 3);
    const int b_sel = (lane >> 3) & 1;

    for (int it = 0; it < nk; ++it) {
        cp_wait<S - 2>();
        __syncthreads();
        load_stage(it + S - 1);
        cp_commit();

        const uint32_t st = sbase + (uint32_t)(it % S) * STAGE;

        #pragma unroll
        for (int kk = 0; kk < 4; ++kk) {
            // A fragments for this k16 slice: 2 m-tiles (per-kk: low regs)
            uint32_t afr[2][4];
            #pragma unroll
            for (int mt = 0; mt < 2; ++mt) {
                const int row  = warp_m + mt * 16 + a_row;
                const int slot = kk * 2 + a_sel;
                ldsm4(afr[mt],
                      st + (uint32_t)row * 128u + (uint32_t)((slot ^ (row & 7)) << 4));
            }

            {   // hi component (f32 acc)
                uint32_t bfr[2][4];
                #pragma unroll
                for (int jn = 0; jn < 2; ++jn) {
                    const int row  = warp_n + jn * 16 + b_row;
                    const int slot = kk * 2 + b_sel;
                    ldsm4(bfr[jn],
                          st + ABYTES + (uint32_t)row * 128u
                             + (uint32_t)((slot ^ (row & 7)) << 4));
                }
                #pragma unroll
                for (int mt = 0; mt < 2; ++mt)
                    #pragma unroll
                    for (int nt = 0; nt < 4; ++nt)
                        mma_f32(acc[mt][nt], afr[mt],
                                bfr[nt >> 1][(nt & 1) * 2],
                                bfr[nt >> 1][(nt & 1) * 2 + 1]);
            }

            {   // residual component (f16 acc)
                uint32_t bfr[2][4];
                #pragma unroll
                for (int jn = 0; jn < 2; ++jn) {
                    const int row  = warp_n + jn * 16 + b_row;
                    const int slot = kk * 2 + b_sel;
                    ldsm4(bfr[jn],
                          st + ABYTES + BCOMP + (uint32_t)row * 128u
                             + (uint32_t)((slot ^ (row & 7)) << 4));
                }
                #pragma unroll
                for (int mt = 0; mt < 2; ++mt)
                    #pragma unroll
                    for (int nt = 0; nt < 4; ++nt)
                        mma_f16(accr[mt][nt], afr[mt],
                                bfr[nt >> 1][(nt & 1) * 2],
                                bfr[nt >> 1][(nt & 1) * 2 + 1]);
            }
        }
    }

    // ---- epilogue: combine, (bias), store fp32 --------------------------------
    constexpr float SC = 1.0f / 256.0f;
    const int col2 = (lane & 3) * 2;
    const int rowg = lane >> 2;
    float* const obase = (MODE == 1)
        ? outp + (size_t)blockIdx.z * MALL * OUTD
        : outp;
    #pragma unroll
    for (int mt = 0; mt < 2; ++mt) {
        #pragma unroll
        for (int nt = 0; nt < 4; ++nt) {
            const int n = n0 + warp_n + nt * 8 + col2;
            const int mbase = m0 + warp_m + mt * 16 + rowg;
            const float2 r01 = __half22float2(*(const __half2*)&accr[mt][nt][0]);
            const float2 r23 = __half22float2(*(const __half2*)&accr[mt][nt][1]);
            float2 v0, v1;
            v0.x = acc[mt][nt][0] + SC * r01.x;
            v0.y = acc[mt][nt][1] + SC * r01.y;
            v1.x = acc[mt][nt][2] + SC * r23.x;
            v1.y = acc[mt][nt][3] + SC * r23.y;
            if (MODE == 0) {
                const float2 bv = *(const float2*)(bias + n);
                v0.x += bv.x; v0.y += bv.y; v1.x += bv.x; v1.y += bv.y;
            }
            *(float2*)(obase + (size_t)mbase * ldn + n)       = v0;
            *(float2*)(obase + (size_t)(mbase + 8) * ldn + n) = v1;
        }
    }
}

// ============================================================================
// LIF scan over all 50 steps for 4096-wide layers (per-neuron independent).
// One 8B spike store per thread per step.
// ============================================================================
__global__ void k_lif_scan(const float4* __restrict__ cur, uint2* __restrict__ s) {
    const int i = blockIdx.x * blockDim.x + threadIdx.x;   // N1/4 threads exact
    float4 mem; mem.x = 0.0f; mem.y = 0.0f; mem.z = 0.0f; mem.w = 0.0f;
    for (int t = 0; t < TSTEPS; ++t) {
        const float4 c = cur[(size_t)t * (N1 / 4) + i];
        mem.x = 0.9f * mem.x + c.x - ((mem.x > 1.0f) ? 1.0f : 0.0f);
        mem.y = 0.9f * mem.y + c.y - ((mem.y > 1.0f) ? 1.0f : 0.0f);
        mem.z = 0.9f * mem.z + c.z - ((mem.z > 1.0f) ? 1.0f : 0.0f);
        mem.w = 0.9f * mem.w + c.w - ((mem.w > 1.0f) ? 1.0f : 0.0f);
        __half2 lo, hi;
        lo.x = __float2half((mem.x > 1.0f) ? 1.0f : 0.0f);
        lo.y = __float2half((mem.y > 1.0f) ? 1.0f : 0.0f);
        hi.x = __float2half((mem.z > 1.0f) ? 1.0f : 0.0f);
        hi.y = __float2half((mem.w > 1.0f) ? 1.0f : 0.0f);
        uint2 pk;
        pk.x = *(const uint32_t*)&lo;
        pk.y = *(const uint32_t*)&hi;
        s[(size_t)t * (N1 / 4) + i] = pk;
    }
}

// ============================================================================
// LIF3: reduce split-K partials + bias, scan, spike-count accumulate.
// ============================================================================
__global__ void k_lif3(const float* __restrict__ part, const float* __restrict__ b3,
                       float* __restrict__ out) {
    const int idx = blockIdx.x * blockDim.x + threadIdx.x;   // 16384 exact
    const int b = idx >> 6;
    const int n = idx & (OUTD - 1);
    const float bv = b3[n];
    float mem = 0.0f, s = 0.0f;
    for (int t = 0; t < TSTEPS; ++t) {
        const size_t moff = (size_t)(t * BATCH + b) * OUTD + n;
        float c = bv;
        #pragma unroll
        for (int z = 0; z < KSPL3; ++z)
            c += part[(size_t)z * MALL * OUTD + moff];
        mem = 0.9f * mem + c - ((mem > 1.0f) ? 1.0f : 0.0f);
        s += ((mem > 1.0f) ? 1.0f : 0.0f);
    }
    out[idx] = s;
}

// ============================================================================
// Prep: spike convert + weight splits, vectorized 2 elems/thread (1 launch)
// ============================================================================
__device__ __forceinline__ void split_one2(const float2* __restrict__ W,
                                           __half2* __restrict__ a,
                                           __half2* __restrict__ b,
                                           int n2, int gid, int st) {
    for (int i = gid; i < n2; i += st) {
        const float2 w = W[i];
        const __half hx = __float2half_rn(w.x);
        const __half hy = __float2half_rn(w.y);
        const float rx = (w.x - __half2float(hx)) * 256.0f;
        const float ry = (w.y - __half2float(hy)) * 256.0f;
        __half2 ha; ha.x = hx; ha.y = hy;
        __half2 hb; hb.x = __float2half_rn(rx); hb.y = __float2half_rn(ry);
        a[i] = ha; b[i] = hb;
    }
}

__global__ void k_prep(const float2* __restrict__ x, __half2* __restrict__ xs, int nx2,
                       const float2* __restrict__ W1, __half2* w1a, __half2* w1b, int n1,
                       const float2* __restrict__ W2, __half2* w2a, __half2* w2b, int n2,
                       const float2* __restrict__ W3, __half2* w3a, __half2* w3b, int n3) {
    const int gid = blockIdx.x * blockDim.x + threadIdx.x;
    const int st  = gridDim.x * blockDim.x;
    for (int i = gid; i < nx2; i += st) {
        const float2 v = x[i];
        __half2 h; h.x = __float2half(v.x); h.y = __float2half(v.y);
        xs[i] = h;
    }
    split_one2(W1, w1a, w1b, n1, gid, st);
    split_one2(W2, w2a, w2b, n2, gid, st);
    split_one2(W3, w3a, w3b, n3, gid, st);
}

// ============================================================================
// Host launcher: 7 kernel launches total.
// ============================================================================
extern "C" void kernel_launch(void* const* d_in, const int* in_sizes, int n_in,
                              void* d_out, int out_size) {
    (void)in_sizes; (void)n_in; (void)out_size;

    const float* spike_seq = (const float*)d_in[0];
    const float* W1 = (const float*)d_in[1];
    const float* b1 = (const float*)d_in[2];
    const float* W2 = (const float*)d_in[3];
    const float* b2 = (const float*)d_in[4];
    const float* W3 = (const float*)d_in[5];
    const float* b3 = (const float*)d_in[6];
    float* out = (float*)d_out;

    void *p_spk, *p_cur, *p_s1a, *p_s2a, *p_part3;
    void *p_w1a, *p_w1b, *p_w2a, *p_w2b, *p_w3a, *p_w3b;
    cudaGetSymbolAddress(&p_spk, g_spk_in);
    cudaGetSymbolAddress(&p_cur, g_cur);
    cudaGetSymbolAddress(&p_s1a, g_s1_all);
    cudaGetSymbolAddress(&p_s2a, g_s2_all);
    cudaGetSymbolAddress(&p_part3, g_part3);
    cudaGetSymbolAddress(&p_w1a, g_W1a); cudaGetSymbolAddress(&p_w1b, g_W1b);
    cudaGetSymbolAddress(&p_w2a, g_W2a); cudaGetSymbolAddress(&p_w2b, g_W2b);
    cudaGetSymbolAddress(&p_w3a, g_W3a); cudaGetSymbolAddress(&p_w3b, g_W3b);

    __half* spkin = (__half*)p_spk;
    float*  cur   = (float*)p_cur;
    __half* s1all = (__half*)p_s1a;
    __half* s2all = (__half*)p_s2a;
    float*  part3 = (float*)p_part3;
    __half *w1a = (__half*)p_w1a, *w1b = (__half*)p_w1b;
    __half *w2a = (__half*)p_w2a, *w2b = (__half*)p_w2b;
    __half *w3a = (__half*)p_w3a, *w3b = (__half*)p_w3b;

    constexpr int SMEM = 3 * (128 * 128 + 2 * 64 * 128);   // 98304 = 96KB
    static int configured = -1;
    if (configured < 0) {
        cudaFuncSetAttribute(gemm_big<0>,
                             cudaFuncAttributeMaxDynamicSharedMemorySize, SMEM);
        cudaFuncSetAttribute(gemm_big<1>,
                             cudaFuncAttributeMaxDynamicSharedMemorySize, SMEM);
        configured = 1;
    }

    // 1) prep (vectorized, 2 elems/thread)
    k_prep<<<1184, 256>>>((const float2*)spike_seq, (__half2*)spkin, MALL * INDIM / 2,
                          (const float2*)W1, (__half2*)w1a, (__half2*)w1b, H1D * INDIM / 2,
                          (const float2*)W2, (__half2*)w2a, (__half2*)w2b, H2D * H1D / 2,
                          (const float2*)W3, (__half2*)w3a, (__half2*)w3b, OUTD * H2D / 2);

    // 2) gemm1_big: cur1 = x @ W1^T + b1   (M=12800, N=4096, K=1536)
    gemm_big<0><<<dim3(MALL / 128, H1D / 64), 256, SMEM>>>(
        spkin, INDIM, w1a, w1b, INDIM, INDIM / 64, b1, cur, H1D);

    // 3) LIF1 scan -> s1_all
    k_lif_scan<<<N1 / 4 / 256, 256>>>((const float4*)cur, (uint2*)s1all);

    // 4) gemm2_big: cur2 = s1_all @ W2^T + b2   (M=12800, N=4096, K=4096)
    gemm_big<0><<<dim3(MALL / 128, H2D / 64), 256, SMEM>>>(
        s1all, H1D, w2a, w2b, H1D, H1D / 64, b2, cur, H2D);

    // 5) LIF2 scan -> s2_all
    k_lif_scan<<<N1 / 4 / 256, 256>>>((const float4*)cur, (uint2*)s2all);

    // 6) gemm3_big: split-K=8 partials   (M=12800, N=64, K=512 per split)
    gemm_big<1><<<dim3(MALL / 128, 1, KSPL3), 256, SMEM>>>(
        s2all, H2D, w3a, w3b, H2D, (H2D / KSPL3) / 64, nullptr, part3, OUTD);

    // 7) LIF3: reduce partials + scan + accumulate
    k_lif3<<<(BATCH * OUTD) / 256, 256>>>(part3, b3, out);
}

// round 17
// speedup vs baseline: 1.0539x; 1.0002x over previous
#include <cuda_runtime.h>
#include <cuda_fp16.h>
#include <cstdint>
#include <cstddef>

// ============================================================================
// SNN, fully batched formulation (7 launches):
//   gemm1_big (M=12800,N=4096,K=1536) -> LIF1 scan -> gemm2_big (K=4096)
//   -> LIF2 scan -> gemm3_big (N=64, split-K=8) -> LIF3 scan (+reduce) -> out
//
// Tensor path (plain sm_103): mma.sync.m16n8k16 + ldmatrix + cp.async.
// Weights split 2-way into fp16 with scaled residual:
//   w = h + m/256,  h = fp16(w), m = fp16(256*(w-h))
// hi comp in FP32 acc; residual in FP16 acc (rel_err = 0 across all rounds).
//
// GEMM core = measured optimum (R12): 256 thr, tile 128x64, warps 4m x 2n,
// warp tile 32x32, 3-stage cp.async ring (K-chunk 64, 32KB/stage, 96KB smem),
// __launch_bounds__(256,2) -> 2 CTAs/SM, 128 regs (full register file:
// 16 warps x 32 x 128 = 64K). ~88% of the fallback-HMMA issue floor; design
// space bracketed (1/2/3 CTAs per SM, warp tiles 32x32/64x32, S=2/3, K64/128)
// -- this configuration is the wall.
// ============================================================================

#define TSTEPS 50
#define BATCH  256
#define INDIM  1536
#define H1D    4096
#define H2D    4096
#define OUTD   64
#define MALL   (TSTEPS * BATCH)       // 12800
#define N1     (BATCH * H1D)          // 1048576
#define KSPL3  8                      // layer-3 split-K

// ---------------- persistent scratch (device globals) -----------------------
__device__ __align__(128) __half g_spk_in[(size_t)MALL * INDIM];
__device__ __align__(128) float  g_cur[(size_t)MALL * H1D];       // reused cur1/cur2
__device__ __align__(128) __half g_s1_all[(size_t)MALL * H1D];
__device__ __align__(128) __half g_s2_all[(size_t)MALL * H2D];
__device__ __align__(128) float  g_part3[(size_t)KSPL3 * MALL * OUTD];
__device__ __align__(128) __half g_W1a[(size_t)H1D * INDIM];
__device__ __align__(128) __half g_W1b[(size_t)H1D * INDIM];
__device__ __align__(128) __half g_W2a[(size_t)H2D * H1D];
__device__ __align__(128) __half g_W2b[(size_t)H2D * H1D];
__device__ __align__(128) __half g_W3a[(size_t)OUTD * H2D];
__device__ __align__(128) __half g_W3b[(size_t)OUTD * H2D];

// ------------------------------ asm helpers ---------------------------------
__device__ __forceinline__ uint32_t smem_u32(const void* p) {
    uint32_t a;
    asm("{ .reg .u64 t; cvta.to.shared.u64 t, %1; cvt.u32.u64 %0, t; }"
        : "=r"(a) : "l"(p));
    return a;
}

__device__ __forceinline__ void cp16(uint32_t smem, const void* gmem) {
    asm volatile("cp.async.cg.shared.global [%0], [%1], 16;"
                 :: "r"(smem), "l"(gmem) : "memory");
}
__device__ __forceinline__ void cp_commit() {
    asm volatile("cp.async.commit_group;" ::: "memory");
}
template<int N>
__device__ __forceinline__ void cp_wait() {
    asm volatile("cp.async.wait_group %0;" :: "n"(N) : "memory");
}

__device__ __forceinline__ void ldsm4(uint32_t (&r)[4], uint32_t addr) {
    asm volatile("ldmatrix.sync.aligned.m8n8.x4.shared.b16 {%0,%1,%2,%3}, [%4];"
                 : "=r"(r[0]), "=r"(r[1]), "=r"(r[2]), "=r"(r[3]) : "r"(addr));
}

__device__ __forceinline__ void mma_f32(float (&d)[4], const uint32_t (&a)[4],
                                        uint32_t b0, uint32_t b1) {
    asm volatile(
        "mma.sync.aligned.m16n8k16.row.col.f32.f16.f16.f32 "
        "{%0,%1,%2,%3}, {%4,%5,%6,%7}, {%8,%9}, {%0,%1,%2,%3};"
        : "+f"(d[0]), "+f"(d[1]), "+f"(d[2]), "+f"(d[3])
        : "r"(a[0]), "r"(a[1]), "r"(a[2]), "r"(a[3]), "r"(b0), "r"(b1));
}

__device__ __forceinline__ void mma_f16(uint32_t (&d)[2], const uint32_t (&a)[4],
                                        uint32_t b0, uint32_t b1) {
    asm volatile(
        "mma.sync.aligned.m16n8k16.row.col.f16.f16.f16.f16 "
        "{%0,%1}, {%2,%3,%4,%5}, {%6,%7}, {%0,%1};"
        : "+r"(d[0]), "+r"(d[1])
        : "r"(a[0]), "r"(a[1]), "r"(a[2]), "r"(a[3]), "r"(b0), "r"(b1));
}

// ============================================================================
// Batched GEMM (R12 core). MODE 0: D = A @ (Wa + Wb/256)^T + bias, fp32 store.
//                        MODE 1: split-K partial (no bias) to part + z*MALL*OUTD.
// CTA: 256 threads, tile M=128 x N=64, warps 4(m) x 2(n), warp tile 32x32.
// 3-stage cp.async ring; stage = K-chunk 64: A 16KB + B 2x8KB = 32KB.
// 96KB smem -> 2 CTAs/SM.
// ============================================================================
template<int MODE>
__global__ void __launch_bounds__(256, 2) gemm_big(
    const __half* __restrict__ A, int lda,
    const __half* __restrict__ Wa,
    const __half* __restrict__ Wb,
    int ldw, int nk,
    const float* __restrict__ bias,
    float* __restrict__ outp, int ldn)
{
    constexpr int S = 3;
    constexpr int ABYTES = 128 * 128;            // 16KB: 128 rows x 64 f16
    constexpr int BCOMP  = 64 * 128;             // 8KB per weight component
    constexpr int STAGE  = ABYTES + 2 * BCOMP;   // 32KB

    extern __shared__ char smem[];
    const uint32_t sbase = smem_u32(smem);

    const int tid  = threadIdx.x;
    const int lane = tid & 31;
    const int wid  = tid >> 5;
    const int m0   = blockIdx.x * 128;
    const int n0   = blockIdx.y * 64;
    const int kbase = (MODE == 1) ? (int)blockIdx.z * nk * 64 : 0;

    const int warp_m = (wid >> 1) * 32;  // 0,32,64,96
    const int warp_n = (wid & 1) * 32;   // 0,32

    // ---- stage loader: K-chunk 64 -------------------------------------------
    auto load_stage = [&](int L) {
        if (L >= nk) return;
        const uint32_t st = sbase + (uint32_t)(L % S) * STAGE;
        const int k0 = kbase + L * 64;
        // A: 1024 16B-slots, 4 per thread
        #pragma unroll
        for (int i = 0; i < 4; ++i) {
            const int idx  = tid + i * 256;
            const int row  = idx >> 3;
            const int slot = idx & 7;
            const char* g = (const char*)(A + (size_t)(m0 + row) * lda + k0) + slot * 16;
            cp16(st + (uint32_t)row * 128u + (uint32_t)((slot ^ (row & 7)) << 4), g);
        }
        // B: 2 comps x 512 slots, 2 per thread per comp
        #pragma unroll
        for (int c = 0; c < 2; ++c) {
            const __half* W = (c == 0) ? Wa : Wb;
            const uint32_t bb = st + ABYTES + (uint32_t)c * BCOMP;
            #pragma unroll
            for (int i = 0; i < 2; ++i) {
                const int idx  = tid + i * 256;
                const int row  = idx >> 3;
                const int slot = idx & 7;
                const char* g = (const char*)(W + (size_t)(n0 + row) * ldw + k0) + slot * 16;
                cp16(bb + (uint32_t)row * 128u + (uint32_t)((slot ^ (row & 7)) << 4), g);
            }
        }
    };

    #pragma unroll
    for (int L = 0; L < S - 1; ++L) { load_stage(L); cp_commit(); }

    float    acc [2][4][4];   // [mt][nt][e]  hi comp, f32
    uint32_t accr[2][4][2];   // [mt][nt]     residual, f16x2
    #pragma unroll
    for (int mt = 0; mt < 2; ++mt)
        #pragma unroll
        for (int nt = 0; nt < 4; ++nt) {
            #pragma unroll
            for (int e = 0; e < 4; ++e) acc[mt][nt][e] = 0.0f;
            accr[mt][nt][0] = 0u; accr[mt][nt][1] = 0u;
        }

    const int a_row = (lane & 7) | (((lane >> 3) & 1) << 3);
    const int a_sel = lane >> 4;
    const int b_row = (lane & 7) | (((lane >> 4) & 1) << 3);
    const int b_sel = (lane >> 3) & 1;

    for (int it = 0; it < nk; ++it) {
        cp_wait<S - 2>();
        __syncthreads();
        load_stage(it + S - 1);
        cp_commit();

        const uint32_t st = sbase + (uint32_t)(it % S) * STAGE;

        #pragma unroll
        for (int kk = 0; kk < 4; ++kk) {
            // A fragments for this k16 slice: 2 m-tiles (per-kk: low regs)
            uint32_t afr[2][4];
            #pragma unroll
            for (int mt = 0; mt < 2; ++mt) {
                const int row  = warp_m + mt * 16 + a_row;
                const int slot = kk * 2 + a_sel;
                ldsm4(afr[mt],
                      st + (uint32_t)row * 128u + (uint32_t)((slot ^ (row & 7)) << 4));
            }

            {   // hi component (f32 acc)
                uint32_t bfr[2][4];
                #pragma unroll
                for (int jn = 0; jn < 2; ++jn) {
                    const int row  = warp_n + jn * 16 + b_row;
                    const int slot = kk * 2 + b_sel;
                    ldsm4(bfr[jn],
                          st + ABYTES + (uint32_t)row * 128u
                             + (uint32_t)((slot ^ (row & 7)) << 4));
                }
                #pragma unroll
                for (int mt = 0; mt < 2; ++mt)
                    #pragma unroll
                    for (int nt = 0; nt < 4; ++nt)
                        mma_f32(acc[mt][nt], afr[mt],
                                bfr[nt >> 1][(nt & 1) * 2],
                                bfr[nt >> 1][(nt & 1) * 2 + 1]);
            }

            {   // residual component (f16 acc)
                uint32_t bfr[2][4];
                #pragma unroll
                for (int jn = 0; jn < 2; ++jn) {
                    const int row  = warp_n + jn * 16 + b_row;
                    const int slot = kk * 2 + b_sel;
                    ldsm4(bfr[jn],
                          st + ABYTES + BCOMP + (uint32_t)row * 128u
                             + (uint32_t)((slot ^ (row & 7)) << 4));
                }
                #pragma unroll
                for (int mt = 0; mt < 2; ++mt)
                    #pragma unroll
                    for (int nt = 0; nt < 4; ++nt)
                        mma_f16(accr[mt][nt], afr[mt],
                                bfr[nt >> 1][(nt & 1) * 2],
                                bfr[nt >> 1][(nt & 1) * 2 + 1]);
            }
        }
    }

    // ---- epilogue: combine, (bias), store fp32 --------------------------------
    constexpr float SC = 1.0f / 256.0f;
    const int col2 = (lane & 3) * 2;
    const int rowg = lane >> 2;
    float* const obase = (MODE == 1)
        ? outp + (size_t)blockIdx.z * MALL * OUTD
        : outp;
    #pragma unroll
    for (int mt = 0; mt < 2; ++mt) {
        #pragma unroll
        for (int nt = 0; nt < 4; ++nt) {
            const int n = n0 + warp_n + nt * 8 + col2;
            const int mbase = m0 + warp_m + mt * 16 + rowg;
            const float2 r01 = __half22float2(*(const __half2*)&accr[mt][nt][0]);
            const float2 r23 = __half22float2(*(const __half2*)&accr[mt][nt][1]);
            float2 v0, v1;
            v0.x = acc[mt][nt][0] + SC * r01.x;
            v0.y = acc[mt][nt][1] + SC * r01.y;
            v1.x = acc[mt][nt][2] + SC * r23.x;
            v1.y = acc[mt][nt][3] + SC * r23.y;
            if (MODE == 0) {
                const float2 bv = *(const float2*)(bias + n);
                v0.x += bv.x; v0.y += bv.y; v1.x += bv.x; v1.y += bv.y;
            }
            *(float2*)(obase + (size_t)mbase * ldn + n)       = v0;
            *(float2*)(obase + (size_t)(mbase + 8) * ldn + n) = v1;
        }
    }
}

// ============================================================================
// LIF scan over all 50 steps for 4096-wide layers (per-neuron independent).
// One 8B spike store per thread per step.
// ============================================================================
__global__ void k_lif_scan(const float4* __restrict__ cur, uint2* __restrict__ s) {
    const int i = blockIdx.x * blockDim.x + threadIdx.x;   // N1/4 threads exact
    float4 mem; mem.x = 0.0f; mem.y = 0.0f; mem.z = 0.0f; mem.w = 0.0f;
    for (int t = 0; t < TSTEPS; ++t) {
        const float4 c = cur[(size_t)t * (N1 / 4) + i];
        mem.x = 0.9f * mem.x + c.x - ((mem.x > 1.0f) ? 1.0f : 0.0f);
        mem.y = 0.9f * mem.y + c.y - ((mem.y > 1.0f) ? 1.0f : 0.0f);
        mem.z = 0.9f * mem.z + c.z - ((mem.z > 1.0f) ? 1.0f : 0.0f);
        mem.w = 0.9f * mem.w + c.w - ((mem.w > 1.0f) ? 1.0f : 0.0f);
        __half2 lo, hi;
        lo.x = __float2half((mem.x > 1.0f) ? 1.0f : 0.0f);
        lo.y = __float2half((mem.y > 1.0f) ? 1.0f : 0.0f);
        hi.x = __float2half((mem.z > 1.0f) ? 1.0f : 0.0f);
        hi.y = __float2half((mem.w > 1.0f) ? 1.0f : 0.0f);
        uint2 pk;
        pk.x = *(const uint32_t*)&lo;
        pk.y = *(const uint32_t*)&hi;
        s[(size_t)t * (N1 / 4) + i] = pk;
    }
}

// ============================================================================
// LIF3: reduce split-K partials + bias, scan, spike-count accumulate.
// ============================================================================
__global__ void k_lif3(const float* __restrict__ part, const float* __restrict__ b3,
                       float* __restrict__ out) {
    const int idx = blockIdx.x * blockDim.x + threadIdx.x;   // 16384 exact
    const int b = idx >> 6;
    const int n = idx & (OUTD - 1);
    const float bv = b3[n];
    float mem = 0.0f, s = 0.0f;
    for (int t = 0; t < TSTEPS; ++t) {
        const size_t moff = (size_t)(t * BATCH + b) * OUTD + n;
        float c = bv;
        #pragma unroll
        for (int z = 0; z < KSPL3; ++z)
            c += part[(size_t)z * MALL * OUTD + moff];
        mem = 0.9f * mem + c - ((mem > 1.0f) ? 1.0f : 0.0f);
        s += ((mem > 1.0f) ? 1.0f : 0.0f);
    }
    out[idx] = s;
}

// ============================================================================
// Prep: spike convert + weight splits, vectorized 2 elems/thread (1 launch)
// ============================================================================
__device__ __forceinline__ void split_one2(const float2* __restrict__ W,
                                           __half2* __restrict__ a,
                                           __half2* __restrict__ b,
                                           int n2, int gid, int st) {
    for (int i = gid; i < n2; i += st) {
        const float2 w = W[i];
        const __half hx = __float2half_rn(w.x);
        const __half hy = __float2half_rn(w.y);
        const float rx = (w.x - __half2float(hx)) * 256.0f;
        const float ry = (w.y - __half2float(hy)) * 256.0f;
        __half2 ha; ha.x = hx; ha.y = hy;
        __half2 hb; hb.x = __float2half_rn(rx); hb.y = __float2half_rn(ry);
        a[i] = ha; b[i] = hb;
    }
}

__global__ void k_prep(const float2* __restrict__ x, __half2* __restrict__ xs, int nx2,
                       const float2* __restrict__ W1, __half2* w1a, __half2* w1b, int n1,
                       const float2* __restrict__ W2, __half2* w2a, __half2* w2b, int n2,
                       const float2* __restrict__ W3, __half2* w3a, __half2* w3b, int n3) {
    const int gid = blockIdx.x * blockDim.x + threadIdx.x;
    const int st  = gridDim.x * blockDim.x;
    for (int i = gid; i < nx2; i += st) {
        const float2 v = x[i];
        __half2 h; h.x = __float2half(v.x); h.y = __float2half(v.y);
        xs[i] = h;
    }
    split_one2(W1, w1a, w1b, n1, gid, st);
    split_one2(W2, w2a, w2b, n2, gid, st);
    split_one2(W3, w3a, w3b, n3, gid, st);
}

// ============================================================================
// Host launcher: 7 kernel launches total.
// ============================================================================
extern "C" void kernel_launch(void* const* d_in, const int* in_sizes, int n_in,
                              void* d_out, int out_size) {
    (void)in_sizes; (void)n_in; (void)out_size;

    const float* spike_seq = (const float*)d_in[0];
    const float* W1 = (const float*)d_in[1];
    const float* b1 = (const float*)d_in[2];
    const float* W2 = (const float*)d_in[3];
    const float* b2 = (const float*)d_in[4];
    const float* W3 = (const float*)d_in[5];
    const float* b3 = (const float*)d_in[6];
    float* out = (float*)d_out;

    void *p_spk, *p_cur, *p_s1a, *p_s2a, *p_part3;
    void *p_w1a, *p_w1b, *p_w2a, *p_w2b, *p_w3a, *p_w3b;
    cudaGetSymbolAddress(&p_spk, g_spk_in);
    cudaGetSymbolAddress(&p_cur, g_cur);
    cudaGetSymbolAddress(&p_s1a, g_s1_all);
    cudaGetSymbolAddress(&p_s2a, g_s2_all);
    cudaGetSymbolAddress(&p_part3, g_part3);
    cudaGetSymbolAddress(&p_w1a, g_W1a); cudaGetSymbolAddress(&p_w1b, g_W1b);
    cudaGetSymbolAddress(&p_w2a, g_W2a); cudaGetSymbolAddress(&p_w2b, g_W2b);
    cudaGetSymbolAddress(&p_w3a, g_W3a); cudaGetSymbolAddress(&p_w3b, g_W3b);

    __half* spkin = (__half*)p_spk;
    float*  cur   = (float*)p_cur;
    __half* s1all = (__half*)p_s1a;
    __half* s2all = (__half*)p_s2a;
    float*  part3 = (float*)p_part3;
    __half *w1a = (__half*)p_w1a, *w1b = (__half*)p_w1b;
    __half *w2a = (__half*)p_w2a, *w2b = (__half*)p_w2b;
    __half *w3a = (__half*)p_w3a, *w3b = (__half*)p_w3b;

    constexpr int SMEM = 3 * (128 * 128 + 2 * 64 * 128);   // 98304 = 96KB
    static int configured = -1;
    if (configured < 0) {
        cudaFuncSetAttribute(gemm_big<0>,
                             cudaFuncAttributeMaxDynamicSharedMemorySize, SMEM);
        cudaFuncSetAttribute(gemm_big<1>,
                             cudaFuncAttributeMaxDynamicSharedMemorySize, SMEM);
        configured = 1;
    }

    // 1) prep (vectorized, 2 elems/thread)
    k_prep<<<1184, 256>>>((const float2*)spike_seq, (__half2*)spkin, MALL * INDIM / 2,
                          (const float2*)W1, (__half2*)w1a, (__half2*)w1b, H1D * INDIM / 2,
                          (const float2*)W2, (__half2*)w2a, (__half2*)w2b, H2D * H1D / 2,
                          (const float2*)W3, (__half2*)w3a, (__half2*)w3b, OUTD * H2D / 2);

    // 2) gemm1_big: cur1 = x @ W1^T + b1   (M=12800, N=4096, K=1536)
    gemm_big<0><<<dim3(MALL / 128, H1D / 64), 256, SMEM>>>(
        spkin, INDIM, w1a, w1b, INDIM, INDIM / 64, b1, cur, H1D);

    // 3) LIF1 scan -> s1_all
    k_lif_scan<<<N1 / 4 / 256, 256>>>((const float4*)cur, (uint2*)s1all);

    // 4) gemm2_big: cur2 = s1_all @ W2^T + b2   (M=12800, N=4096, K=4096)
    gemm_big<0><<<dim3(MALL / 128, H2D / 64), 256, SMEM>>>(
        s1all, H1D, w2a, w2b, H1D, H1D / 64, b2, cur, H2D);

    // 5) LIF2 scan -> s2_all
    k_lif_scan<<<N1 / 4 / 256, 256>>>((const float4*)cur, (uint2*)s2all);

    // 6) gemm3_big: split-K=8 partials   (M=12800, N=64, K=512 per split)
    gemm_big<1><<<dim3(MALL / 128, 1, KSPL3), 256, SMEM>>>(
        s2all, H2D, w3a, w3b, H2D, (H2D / KSPL3) / 64, nullptr, part3, OUTD);

    // 7) LIF3: reduce partials + scan + accumulate
    k_lif3<<<(BATCH * OUTD) / 256, 256>>>(part3, b3, out);
}